// round 10
// baseline (speedup 1.0000x reference)
#include <cuda_runtime.h>
#include <cuda_fp16.h>
#include <cstdint>

#define BATCH 65536
#define DIN   784
#define DH    320
#define DOUT  10
#define THRESH 0.001f
#define MARGIN 0.035f
#define CAP    (1 << 20)

// GEMM1: persistent CTAs, B-stationary.
// grid (4 bands, 37). CTA: 512 thr / 16 warps = 2 Kgroups x (4M x 2N).
#define BM 128
#define BAND 80
#define KC 64
#define NFULL 12            // 12 x 64 + 16 = 784
#define NMT 512             // M tiles total
#define YSTRIDE 37
#define ABUF 16384          // 128 rows x 128B, swizzled chunk c at r*128+((c^(r&7))<<4)
#define BROWSTR 1584        // 784 halves (1568B) + 16B pad
#define BBYTES (BAND*BROWSTR)            // 126720
#define SCR_OFF (2*ABUF + BBYTES)        // 159488
#define B1S_OFF (SCR_OFF + BM*BAND*4)    // +40960 = 200448
#define SMEM_DYN (B1S_OFF + BAND*4)      // 200768

__device__ __align__(16) int8_t   g_h[(size_t)BATCH * DH];
__device__ __align__(16) __half   g_w1h[(size_t)DH * DIN];
__device__ __align__(16) uint32_t g_list[CAP];
__device__ int g_cnt;

__device__ __forceinline__ int tern_i(float v) {
    return v > THRESH ? 1 : (v < -THRESH ? -1 : 0);
}
__device__ __forceinline__ uint32_t h2u(__half2 h) {
    return *reinterpret_cast<uint32_t*>(&h);
}
__device__ __forceinline__ uint32_t smem_u32(const void* p) {
    uint32_t a;
    asm("{ .reg .u64 t; cvta.to.shared.u64 t, %1; cvt.u32.u64 %0, t; }" : "=r"(a) : "l"(p));
    return a;
}
__device__ __forceinline__ void mma16816(float* c, uint32_t a0, uint32_t a1,
                                         uint32_t a2, uint32_t a3,
                                         uint32_t b0, uint32_t b1) {
    asm volatile(
        "mma.sync.aligned.m16n8k16.row.col.f32.f16.f16.f32 "
        "{%0,%1,%2,%3}, {%4,%5,%6,%7}, {%8,%9}, {%0,%1,%2,%3};"
        : "+f"(c[0]), "+f"(c[1]), "+f"(c[2]), "+f"(c[3])
        : "r"(a0), "r"(a1), "r"(a2), "r"(a3), "r"(b0), "r"(b1));
}
__device__ __forceinline__ void ldsm4(uint32_t& r0, uint32_t& r1,
                                      uint32_t& r2, uint32_t& r3, uint32_t a) {
    asm volatile("ldmatrix.sync.aligned.m8n8.x4.shared.b16 {%0,%1,%2,%3}, [%4];"
                 : "=r"(r0), "=r"(r1), "=r"(r2), "=r"(r3) : "r"(a));
}
__device__ __forceinline__ void ldsm2(uint32_t& r0, uint32_t& r1, uint32_t a) {
    asm volatile("ldmatrix.sync.aligned.m8n8.x2.shared.b16 {%0,%1}, [%2];"
                 : "=r"(r0), "=r"(r1) : "r"(a));
}
__device__ __forceinline__ void sts128(uint32_t a, uint32_t x, uint32_t y,
                                       uint32_t z, uint32_t w) {
    asm volatile("st.shared.v4.b32 [%0], {%1,%2,%3,%4};" :: "r"(a), "r"(x), "r"(y), "r"(z), "r"(w));
}
__device__ __forceinline__ void cpasync16(uint32_t s, const void* g) {
    asm volatile("cp.async.cg.shared.global [%0], [%1], 16;" :: "r"(s), "l"(g));
}
#define CP_COMMIT() asm volatile("cp.async.commit_group;" ::: "memory")
#define CP_WAIT0()  asm volatile("cp.async.wait_group 0;" ::: "memory")

// ============================================================================
__global__ void prep_w1(const float* __restrict__ w1) {
    if (blockIdx.x == 0 && threadIdx.x == 0) g_cnt = 0;
    int i = blockIdx.x * 256 + threadIdx.x;
    if (i >= DH * DIN / 2) return;
    float a = w1[2 * i], b = w1[2 * i + 1];
    reinterpret_cast<__half2*>(g_w1h)[i] =
        __floats2half2_rn((float)tern_i(a), (float)tern_i(b));
}

// ============================================================================
__global__ __launch_bounds__(512, 1)
void gemm1_persist(const float* __restrict__ x, const float* __restrict__ b1) {
    extern __shared__ __align__(16) uint8_t sm[];
    const uint32_t abase = smem_u32(sm);
    const uint32_t bbase = abase + 2 * ABUF;
    float* b1s = (float*)(sm + B1S_OFF);

    const int tid  = threadIdx.x;
    const int lane = tid & 31;
    const int wid  = tid >> 5;
    const int km   = wid >> 3;       // K-group 0/1
    const int rem  = wid & 7;
    const int wm   = rem >> 1;       // M band 0..3
    const int wn   = rem & 1;        // N band 0..1
    const int g    = lane >> 2;
    const int tg   = lane & 3;
    const int band = blockIdx.x;
    const int n0   = band * BAND;

    if (tid < BAND) b1s[tid] = b1[n0 + tid];

    // ---- load resident B band once: 80 rows x 98 x 16B ----
    for (int i = tid; i < BAND * 98; i += 512) {
        int row = i / 98, c = i % 98;
        cpasync16(bbase + (uint32_t)(row * BROWSTR + c * 16),
                  g_w1h + (size_t)(n0 + row) * DIN + c * 8);
    }
    CP_COMMIT();

    // ---- frag addresses ----
    const int cxor = lane & 7;
    const int chi  = lane >> 4;
    uint32_t arow[2];
#pragma unroll
    for (int mi = 0; mi < 2; mi++)
        arow[mi] = (uint32_t)((wm * 32 + mi * 16 + (lane & 15)) * 128);
    uint32_t bno[2];
#pragma unroll
    for (int j = 0; j < 2; j++)
        bno[j] = bbase + (uint32_t)((wn * 40 + j * 16 + (lane & 7) + ((lane >> 4) & 1) * 8) * BROWSTR
                                    + ((lane >> 3) & 1) * 16);
    const uint32_t bno2 = bbase + (uint32_t)((wn * 40 + 32 + (lane & 7)) * BROWSTR
                                             + ((lane >> 3) & 1) * 16);

    const int ar = tid >> 2;         // 0..127
    const int aq = tid & 3;          // 16-fp32 quarter

    CP_WAIT0();
    __syncthreads();                 // B resident

    float4 v0, v1, v2, v3;
    float acc[2][5][4];

    auto STOREA = [&](int buf, int full) {
        if (aq == 0 || full) {
            const uint32_t ab = abase + (uint32_t)buf * ABUF + (uint32_t)(ar * 128);
            const int sw = ar & 7;
            __half2 h0 = __floats2half2_rn(v0.x, v0.y), h1 = __floats2half2_rn(v0.z, v0.w);
            __half2 h2 = __floats2half2_rn(v1.x, v1.y), h3 = __floats2half2_rn(v1.z, v1.w);
            __half2 h4 = __floats2half2_rn(v2.x, v2.y), h5 = __floats2half2_rn(v2.z, v2.w);
            __half2 h6 = __floats2half2_rn(v3.x, v3.y), h7 = __floats2half2_rn(v3.z, v3.w);
            sts128(ab + (uint32_t)(((aq * 2)     ^ sw) << 4), h2u(h0), h2u(h1), h2u(h2), h2u(h3));
            sts128(ab + (uint32_t)(((aq * 2 + 1) ^ sw) << 4), h2u(h4), h2u(h5), h2u(h6), h2u(h7));
        }
    };

    auto KSTEP = [&](int buf, int ks, int kk16) {
        const uint32_t ab = abase + (uint32_t)buf * ABUF;
        const uint32_t boff = (uint32_t)(kk16 * 32);
        uint32_t bf[10];
        ldsm4(bf[0], bf[1], bf[2], bf[3], bno[0] + boff);
        ldsm4(bf[4], bf[5], bf[6], bf[7], bno[1] + boff);
        ldsm2(bf[8], bf[9], bno2 + boff);
#pragma unroll
        for (int mi = 0; mi < 2; mi++) {
            uint32_t a0, a1, a2, a3;
            const uint32_t co = (uint32_t)(((ks * 2 + chi) ^ cxor) << 4);
            ldsm4(a0, a1, a2, a3, ab + arow[mi] + co);
#pragma unroll
            for (int ni = 0; ni < 5; ni++)
                mma16816(acc[mi][ni], a0, a1, a2, a3, bf[2 * ni], bf[2 * ni + 1]);
        }
    };

    // ================= persistent M-tile loop =================
    for (int mt = blockIdx.y; mt < NMT; mt += YSTRIDE) {
        const int m0 = mt * BM;
        const float* xrow = x + (size_t)(m0 + ar) * DIN + aq * 16;

#pragma unroll
        for (int mi = 0; mi < 2; mi++)
#pragma unroll
            for (int ni = 0; ni < 5; ni++)
#pragma unroll
                for (int e = 0; e < 4; e++) acc[mi][ni][e] = 0.0f;

        // prologue: stage 0
        {
            const float4* p = (const float4*)xrow;
            v0 = p[0]; v1 = p[1]; v2 = p[2]; v3 = p[3];
        }
        STOREA(0, 1);
        __syncthreads();

        for (int kt = 0; kt < NFULL; kt++) {
            const int buf  = kt & 1;
            const int full = (kt + 1 < NFULL) ? 1 : 0;
            if (aq == 0 || full) {
                const float4* p = (const float4*)(xrow + (kt + 1) * KC);
                v0 = p[0]; v1 = p[1]; v2 = p[2]; v3 = p[3];
            }
            if (km == 0) {
                KSTEP(buf, 0, kt * 4 + 0);
                KSTEP(buf, 1, kt * 4 + 1);
            } else {
                KSTEP(buf, 2, kt * 4 + 2);
                KSTEP(buf, 3, kt * 4 + 3);
            }
            STOREA(buf ^ 1, full);
            __syncthreads();
        }
        if (km == 0) KSTEP(0, 0, 48);   // tail K=16
        __syncthreads();

        // ---- K-group reduction via scratch ----
        float4* sp = (float4*)(sm + SCR_OFF);
        const int tk = rem * 32 + lane;
        if (km == 1) {
#pragma unroll
            for (int mi = 0; mi < 2; mi++)
#pragma unroll
                for (int ni = 0; ni < 5; ni++)
                    sp[tk * 10 + mi * 5 + ni] =
                        make_float4(acc[mi][ni][0], acc[mi][ni][1],
                                    acc[mi][ni][2], acc[mi][ni][3]);
        }
        __syncthreads();

        if (km == 0) {
            int cnt = 0;
#pragma unroll
            for (int mi = 0; mi < 2; mi++)
#pragma unroll
                for (int ni = 0; ni < 5; ni++) {
                    float4 o = sp[tk * 10 + mi * 5 + ni];
                    acc[mi][ni][0] += o.x; acc[mi][ni][1] += o.y;
                    acc[mi][ni][2] += o.z; acc[mi][ni][3] += o.w;
                }
#pragma unroll
            for (int mi = 0; mi < 2; mi++) {
                const int r0 = m0 + wm * 32 + mi * 16 + g;
#pragma unroll
                for (int ni = 0; ni < 5; ni++) {
                    const int col = wn * 40 + ni * 8 + tg * 2;
                    const float bv0 = b1s[col], bv1 = b1s[col + 1];
                    float w0 = acc[mi][ni][0] + bv0, w1v = acc[mi][ni][1] + bv1;
                    float w2v = acc[mi][ni][2] + bv0, w3 = acc[mi][ni][3] + bv1;
                    char2 c01, c23;
                    c01.x = (signed char)tern_i(w0); c01.y = (signed char)tern_i(w1v);
                    c23.x = (signed char)tern_i(w2v); c23.y = (signed char)tern_i(w3);
                    *(char2*)(g_h + (size_t)r0 * DH + n0 + col)       = c01;
                    *(char2*)(g_h + (size_t)(r0 + 8) * DH + n0 + col) = c23;
                    cnt += (fabsf(fabsf(w0) - THRESH) < MARGIN);
                    cnt += (fabsf(fabsf(w1v) - THRESH) < MARGIN);
                    cnt += (fabsf(fabsf(w2v) - THRESH) < MARGIN);
                    cnt += (fabsf(fabsf(w3) - THRESH) < MARGIN);
                }
            }
            int incl = cnt;
#pragma unroll
            for (int d = 1; d < 32; d <<= 1) {
                int t = __shfl_up_sync(0xFFFFFFFFu, incl, d);
                if (lane >= d) incl += t;
            }
            const int excl = incl - cnt;
            const int tot  = __shfl_sync(0xFFFFFFFFu, incl, 31);
            if (tot) {
                int base = 0;
                if (lane == 0) base = atomicAdd(&g_cnt, tot);
                base = __shfl_sync(0xFFFFFFFFu, base, 0);
                int p = base + excl;
#pragma unroll
                for (int mi = 0; mi < 2; mi++) {
                    const int r0 = m0 + wm * 32 + mi * 16 + g;
#pragma unroll
                    for (int ni = 0; ni < 5; ni++) {
                        const int col = wn * 40 + ni * 8 + tg * 2;
                        const float bv0 = b1s[col], bv1 = b1s[col + 1];
                        const float vv[4] = { acc[mi][ni][0] + bv0, acc[mi][ni][1] + bv1,
                                              acc[mi][ni][2] + bv0, acc[mi][ni][3] + bv1 };
                        const int rr[4] = { r0, r0, r0 + 8, r0 + 8 };
                        const int cc[4] = { col, col + 1, col, col + 1 };
#pragma unroll
                        for (int e = 0; e < 4; e++) {
                            if (fabsf(fabsf(vv[e]) - THRESH) < MARGIN) {
                                if (p < CAP)
                                    g_list[p] = ((uint32_t)rr[e] << 9) | (uint32_t)(n0 + cc[e]);
                                p++;
                            }
                        }
                    }
                }
            }
        }
        __syncthreads();
    }
}

// ============================================================================
// Correction: exact fp32 recompute of flagged h elements.
// ============================================================================
__global__ __launch_bounds__(256)
void corr_kernel(const float* __restrict__ x, const float* __restrict__ b1) {
    const int lane = threadIdx.x & 31;
    const int wg   = (blockIdx.x * 256 + threadIdx.x) >> 5;
    const int nw   = (gridDim.x * 256) >> 5;
    int total = g_cnt;
    if (total > CAP) total = CAP;

    for (int e = wg; e < total; e += nw) {
        const uint32_t u = g_list[e];
        const int row = (int)(u >> 9);
        const int n   = (int)(u & 511);
        const float4*  xr = (const float4*)(x + (size_t)row * DIN);
        const __half2* wr = (const __half2*)(g_w1h + (size_t)n * DIN);
        float s = 0.0f;
#pragma unroll
        for (int i = 0; i < 6; i++) {
            const int idx = lane + i * 32;
            float4  v  = xr[idx];
            __half2 wa = wr[idx * 2];
            __half2 wb = wr[idx * 2 + 1];
            float2 fa = __half22float2(wa), fb = __half22float2(wb);
            s += v.x * fa.x + v.y * fa.y + v.z * fb.x + v.w * fb.y;
        }
        if (lane < 4) {
            const int idx = 192 + lane;
            float4  v  = xr[idx];
            __half2 wa = wr[idx * 2];
            __half2 wb = wr[idx * 2 + 1];
            float2 fa = __half22float2(wa), fb = __half22float2(wb);
            s += v.x * fa.x + v.y * fa.y + v.z * fb.x + v.w * fb.y;
        }
#pragma unroll
        for (int d = 16; d; d >>= 1)
            s += __shfl_xor_sync(0xFFFFFFFFu, s, d);
        if (lane == 0)
            g_h[(size_t)row * DH + n] = (int8_t)tern_i(s + b1[n]);
    }
}

// ============================================================================
// Head: logits = g_h @ tern(w2)^T + b2 ; log_softmax. 4 threads per row.
// ============================================================================
__global__ __launch_bounds__(256)
void head_kernel(const float* __restrict__ w2,
                 const float* __restrict__ b2,
                 float* __restrict__ out) {
    __shared__ int   q2p[DOUT][DH / 4];
    __shared__ float b2s[DOUT];

    const int tid = threadIdx.x;
    for (int i = tid; i < DOUT * (DH / 4); i += 256) {
        const int o = i / (DH / 4);
        const int w = i % (DH / 4);
        int word = 0;
#pragma unroll
        for (int j = 0; j < 4; j++) {
            int t = tern_i(w2[o * DH + w * 4 + j]);
            word |= (t & 0xFF) << (8 * j);
        }
        q2p[o][w] = word;
    }
    if (tid < DOUT) b2s[tid] = b2[tid];
    __syncthreads();

    const int gidx   = blockIdx.x * 256 + tid;
    const size_t row = (size_t)(gidx >> 2);
    const int q      = gidx & 3;
    const uint4* hp  = (const uint4*)(g_h + row * DH) + q * 5;

    int acc[DOUT];
#pragma unroll
    for (int o = 0; o < DOUT; o++) acc[o] = 0;

#pragma unroll
    for (int c = 0; c < 5; c++) {
        uint4 v = hp[c];
        const int w = q * 20 + c * 4;
#pragma unroll
        for (int o = 0; o < DOUT; o++) {
            acc[o] = __dp4a((int)v.x, q2p[o][w + 0], acc[o]);
            acc[o] = __dp4a((int)v.y, q2p[o][w + 1], acc[o]);
            acc[o] = __dp4a((int)v.z, q2p[o][w + 2], acc[o]);
            acc[o] = __dp4a((int)v.w, q2p[o][w + 3], acc[o]);
        }
    }
#pragma unroll
    for (int o = 0; o < DOUT; o++) {
        acc[o] += __shfl_xor_sync(0xFFFFFFFFu, acc[o], 1);
        acc[o] += __shfl_xor_sync(0xFFFFFFFFu, acc[o], 2);
    }

    if (q == 0) {
        float lg[DOUT];
        float m = -1e30f;
#pragma unroll
        for (int o = 0; o < DOUT; o++) {
            lg[o] = (float)acc[o] + b2s[o];
            m = fmaxf(m, lg[o]);
        }
        float s = 0.0f;
#pragma unroll
        for (int o = 0; o < DOUT; o++) s += expf(lg[o] - m);
        const float lse = m + logf(s);
        float* op = out + row * DOUT;
#pragma unroll
        for (int o = 0; o < DOUT; o++) op[o] = lg[o] - lse;
    }
}

// ============================================================================
extern "C" void kernel_launch(void* const* d_in, const int* in_sizes, int n_in,
                              void* d_out, int out_size) {
    const float* x  = (const float*)d_in[0];
    const float* w1 = (const float*)d_in[1];
    const float* b1 = (const float*)d_in[2];
    const float* w2 = (const float*)d_in[3];
    const float* b2 = (const float*)d_in[4];
    float* out = (float*)d_out;

    cudaFuncSetAttribute(gemm1_persist,
                         cudaFuncAttributeMaxDynamicSharedMemorySize, SMEM_DYN);

    prep_w1<<<(DH * DIN / 2 + 255) / 256, 256>>>(w1);
    gemm1_persist<<<dim3(4, YSTRIDE), 512, SMEM_DYN>>>(x, b1);
    corr_kernel<<<2048, 256>>>(x, b1);
    head_kernel<<<BATCH * 4 / 256, 256>>>(w2, b2, out);
}

// round 11
// speedup vs baseline: 2.9275x; 2.9275x over previous
#include <cuda_runtime.h>
#include <cuda_fp16.h>
#include <cstdint>

#define BATCH 65536
#define DIN   784
#define DH    320
#define DOUT  10
#define THRESH 0.001f
#define MARGIN 0.035f
#define CAP    (1 << 20)

// GEMM1: CTA 128x320 (full N), 512 thr / 16 warps (4M x 4N), K=32/stage,
// single fp16 plane + correction pass.
#define BM 128
#define KC 32
#define NST 25              // 24 x 32 + 16 = 784
#define ABUF 8192           // 128 rows x 64B (4 chunks 16B, swizzle c^((r>>1)&3))
#define BSTR 80             // 64B data + 16B pad per B row
#define BBUF (DH*BSTR)      // 25600
#define B1S_OFF (2*ABUF + 2*BBUF)        // 67584
#define SMEM_DYN (B1S_OFF + DH*4)        // 68864

__device__ __align__(16) int8_t   g_h[(size_t)BATCH * DH];
__device__ __align__(16) __half   g_w1h[(size_t)DH * DIN];
__device__ __align__(16) uint32_t g_list[CAP];
__device__ int g_cnt;

__device__ __forceinline__ int tern_i(float v) {
    return v > THRESH ? 1 : (v < -THRESH ? -1 : 0);
}
__device__ __forceinline__ uint32_t h2u(__half2 h) {
    return *reinterpret_cast<uint32_t*>(&h);
}
__device__ __forceinline__ uint32_t smem_u32(const void* p) {
    uint32_t a;
    asm("{ .reg .u64 t; cvta.to.shared.u64 t, %1; cvt.u32.u64 %0, t; }" : "=r"(a) : "l"(p));
    return a;
}
__device__ __forceinline__ void mma16816(float* c, uint32_t a0, uint32_t a1,
                                         uint32_t a2, uint32_t a3,
                                         uint32_t b0, uint32_t b1) {
    asm volatile(
        "mma.sync.aligned.m16n8k16.row.col.f32.f16.f16.f32 "
        "{%0,%1,%2,%3}, {%4,%5,%6,%7}, {%8,%9}, {%0,%1,%2,%3};"
        : "+f"(c[0]), "+f"(c[1]), "+f"(c[2]), "+f"(c[3])
        : "r"(a0), "r"(a1), "r"(a2), "r"(a3), "r"(b0), "r"(b1));
}
__device__ __forceinline__ void ldsm4(uint32_t& r0, uint32_t& r1,
                                      uint32_t& r2, uint32_t& r3, uint32_t a) {
    asm volatile("ldmatrix.sync.aligned.m8n8.x4.shared.b16 {%0,%1,%2,%3}, [%4];"
                 : "=r"(r0), "=r"(r1), "=r"(r2), "=r"(r3) : "r"(a));
}
__device__ __forceinline__ void sts128(uint32_t a, uint32_t x, uint32_t y,
                                       uint32_t z, uint32_t w) {
    asm volatile("st.shared.v4.b32 [%0], {%1,%2,%3,%4};" :: "r"(a), "r"(x), "r"(y), "r"(z), "r"(w));
}
__device__ __forceinline__ void cpasync16(uint32_t s, const void* g, int pred) {
    asm volatile(
        "{ .reg .pred p; setp.ne.b32 p, %2, 0;\n\t"
        "@p cp.async.cg.shared.global [%0], [%1], 16; }\n"
        :: "r"(s), "l"(g), "r"(pred));
}
#define CP_COMMIT() asm volatile("cp.async.commit_group;" ::: "memory")
#define CP_WAIT0()  asm volatile("cp.async.wait_group 0;" ::: "memory")

// ============================================================================
__global__ void prep_w1(const float* __restrict__ w1) {
    if (blockIdx.x == 0 && threadIdx.x == 0) g_cnt = 0;
    int i = blockIdx.x * 256 + threadIdx.x;
    if (i >= DH * DIN / 2) return;
    float a = w1[2 * i], b = w1[2 * i + 1];
    reinterpret_cast<__half2*>(g_w1h)[i] =
        __floats2half2_rn((float)tern_i(a), (float)tern_i(b));
}

// ============================================================================
// A smem: row r, chunk c(0..3, 16B) at r*64 + ((c ^ ((r>>1)&3))<<4)
// B smem: row n stride 80B, chunk c(0..3) at n*80 + c*16
// ============================================================================
__global__ __launch_bounds__(512, 1)
void gemm1_hmma(const float* __restrict__ x, const float* __restrict__ b1) {
    extern __shared__ __align__(16) uint8_t sm[];
    const uint32_t abase = smem_u32(sm);
    const uint32_t bbase = abase + 2 * ABUF;
    float* b1s = (float*)(sm + B1S_OFF);

    const int tid  = threadIdx.x;
    const int lane = tid & 31;
    const int wid  = tid >> 5;
    const int wm   = wid >> 2;       // M band 0..3 (32 rows)
    const int wn   = wid & 3;        // N band 0..3 (80 cols)
    const int g    = lane >> 2;
    const int tg   = lane & 3;
    const int m0   = blockIdx.x * BM;

    if (tid < DH) b1s[tid] = b1[tid];
    if (tid + 192 < DH) b1s[tid + 192] = b1[tid + 192];   // covers 320 with 512 threads? tid<320 handles all
    // (tid < DH already covers 0..319 since blockDim=512)

    float acc[2][10][4];
#pragma unroll
    for (int mi = 0; mi < 2; mi++)
#pragma unroll
        for (int ni = 0; ni < 10; ni++)
#pragma unroll
            for (int e = 0; e < 4; e++) acc[mi][ni][e] = 0.0f;

    // ---- frag addresses ----
    const int chi = lane >> 4;
    uint32_t arow[2];
    int sxor[2];
#pragma unroll
    for (int mi = 0; mi < 2; mi++) {
        const int r = wm * 32 + mi * 16 + (lane & 15);
        arow[mi] = (uint32_t)(r * 64);
        sxor[mi] = (r >> 1) & 3;
    }
    uint32_t bno[5];
#pragma unroll
    for (int j = 0; j < 5; j++)
        bno[j] = bbase + (uint32_t)((wn * 80 + j * 16 + (lane & 7) + ((lane >> 4) & 1) * 8) * BSTR
                                    + ((lane >> 3) & 1) * 16);

    // ---- A gmem staging: thread = (row ar, 8-fp32 k-octet aq) ----
    const int ar = tid >> 2;         // 0..127
    const int aq = tid & 3;          // k: aq*8 .. aq*8+7
    const float* xrow = x + (size_t)(m0 + ar) * DIN + aq * 8;
    float4 v0, v1;

    auto LOADA = [&](int k0, int full) {
        if (aq < 2 || full) {
            const float4* p = (const float4*)(xrow + k0);
            v0 = p[0]; v1 = p[1];
        }
    };
    auto ISSUEB = [&](int k0, int buf, int full) {
        const uint32_t bb = bbase + (uint32_t)buf * BBUF;
#pragma unroll
        for (int i = 0; i < 3; i++) {
            int idx = tid + i * 512;
            int row = idx >> 2, ch = idx & 3;
            int ok  = (idx < 1280) && (full || ch < 2);
            cpasync16(bb + (uint32_t)(row * BSTR + ch * 16),
                      g_w1h + (size_t)(ok ? row : 0) * DIN + k0 + (ok ? ch : 0) * 8,
                      ok);
        }
        CP_COMMIT();
    };
    auto STOREA = [&](int buf, int full) {
        if (aq < 2 || full) {
            const uint32_t ab = abase + (uint32_t)buf * ABUF + (uint32_t)(ar * 64);
            const int sw = (ar >> 1) & 3;
            __half2 h0 = __floats2half2_rn(v0.x, v0.y);
            __half2 h1 = __floats2half2_rn(v0.z, v0.w);
            __half2 h2 = __floats2half2_rn(v1.x, v1.y);
            __half2 h3 = __floats2half2_rn(v1.z, v1.w);
            sts128(ab + (uint32_t)((aq ^ sw) << 4), h2u(h0), h2u(h1), h2u(h2), h2u(h3));
        }
    };

    auto KSTEP = [&](int buf, int ks) {
        const uint32_t ab = abase + (uint32_t)buf * ABUF;
        const uint32_t boff = (uint32_t)(buf * BBUF + ks * 32);
        uint32_t bf[20];
#pragma unroll
        for (int j = 0; j < 5; j++)
            ldsm4(bf[4 * j], bf[4 * j + 1], bf[4 * j + 2], bf[4 * j + 3],
                  bno[j] + boff);
#pragma unroll
        for (int mi = 0; mi < 2; mi++) {
            uint32_t a0, a1, a2, a3;
            const uint32_t co = (uint32_t)(((ks * 2 + chi) ^ sxor[mi]) << 4);
            ldsm4(a0, a1, a2, a3, ab + arow[mi] + co);
#pragma unroll
            for (int ni = 0; ni < 10; ni++)
                mma16816(acc[mi][ni], a0, a1, a2, a3, bf[2 * ni], bf[2 * ni + 1]);
        }
    };

    // ---- pipeline ----
    ISSUEB(0, 0, 1);
    LOADA(0, 1);
    STOREA(0, 1);
    CP_WAIT0();
    __syncthreads();

    for (int kt = 0; kt < NST - 1; kt++) {
        const int buf  = kt & 1;
        const int full = (kt + 1 < NST - 1) ? 1 : 0;
        ISSUEB((kt + 1) * KC, buf ^ 1, full);
        LOADA((kt + 1) * KC, full);
        KSTEP(buf, 0);
        KSTEP(buf, 1);
        STOREA(buf ^ 1, full);
        CP_WAIT0();
        __syncthreads();
    }
    KSTEP(0, 0);   // tail stage: K=16, buf 0

    // ---- epilogue: +b1, provisional ternarize, flag near-threshold ----
    int cnt = 0;
#pragma unroll
    for (int mi = 0; mi < 2; mi++) {
        const int r0 = m0 + wm * 32 + mi * 16 + g;
#pragma unroll
        for (int ni = 0; ni < 10; ni++) {
            const int col = wn * 80 + ni * 8 + tg * 2;
            const float bv0 = b1s[col], bv1 = b1s[col + 1];
            float w0 = acc[mi][ni][0] + bv0, w1v = acc[mi][ni][1] + bv1;
            float w2v = acc[mi][ni][2] + bv0, w3 = acc[mi][ni][3] + bv1;
            char2 c01, c23;
            c01.x = (signed char)tern_i(w0); c01.y = (signed char)tern_i(w1v);
            c23.x = (signed char)tern_i(w2v); c23.y = (signed char)tern_i(w3);
            *(char2*)(g_h + (size_t)r0 * DH + col)       = c01;
            *(char2*)(g_h + (size_t)(r0 + 8) * DH + col) = c23;
            cnt += (fabsf(fabsf(w0) - THRESH) < MARGIN);
            cnt += (fabsf(fabsf(w1v) - THRESH) < MARGIN);
            cnt += (fabsf(fabsf(w2v) - THRESH) < MARGIN);
            cnt += (fabsf(fabsf(w3) - THRESH) < MARGIN);
        }
    }
    int incl = cnt;
#pragma unroll
    for (int d = 1; d < 32; d <<= 1) {
        int t = __shfl_up_sync(0xFFFFFFFFu, incl, d);
        if (lane >= d) incl += t;
    }
    const int excl = incl - cnt;
    const int tot  = __shfl_sync(0xFFFFFFFFu, incl, 31);
    if (tot) {
        int base = 0;
        if (lane == 0) base = atomicAdd(&g_cnt, tot);
        base = __shfl_sync(0xFFFFFFFFu, base, 0);
        int p = base + excl;
#pragma unroll
        for (int mi = 0; mi < 2; mi++) {
            const int r0 = m0 + wm * 32 + mi * 16 + g;
#pragma unroll
            for (int ni = 0; ni < 10; ni++) {
                const int col = wn * 80 + ni * 8 + tg * 2;
                const float bv0 = b1s[col], bv1 = b1s[col + 1];
                const float vv[4] = { acc[mi][ni][0] + bv0, acc[mi][ni][1] + bv1,
                                      acc[mi][ni][2] + bv0, acc[mi][ni][3] + bv1 };
                const int rr[4] = { r0, r0, r0 + 8, r0 + 8 };
                const int cc[4] = { col, col + 1, col, col + 1 };
#pragma unroll
                for (int e = 0; e < 4; e++) {
                    if (fabsf(fabsf(vv[e]) - THRESH) < MARGIN) {
                        if (p < CAP)
                            g_list[p] = ((uint32_t)rr[e] << 9) | (uint32_t)cc[e];
                        p++;
                    }
                }
            }
        }
    }
}

// ============================================================================
// Correction: exact fp32 recompute of flagged h elements.
// ============================================================================
__global__ __launch_bounds__(256)
void corr_kernel(const float* __restrict__ x, const float* __restrict__ b1) {
    const int lane = threadIdx.x & 31;
    const int wg   = (blockIdx.x * 256 + threadIdx.x) >> 5;
    const int nw   = (gridDim.x * 256) >> 5;
    int total = g_cnt;
    if (total > CAP) total = CAP;

    for (int e = wg; e < total; e += nw) {
        const uint32_t u = g_list[e];
        const int row = (int)(u >> 9);
        const int n   = (int)(u & 511);
        const float4*  xr = (const float4*)(x + (size_t)row * DIN);
        const __half2* wr = (const __half2*)(g_w1h + (size_t)n * DIN);
        float s = 0.0f;
#pragma unroll
        for (int i = 0; i < 6; i++) {
            const int idx = lane + i * 32;
            float4  v  = xr[idx];
            __half2 wa = wr[idx * 2];
            __half2 wb = wr[idx * 2 + 1];
            float2 fa = __half22float2(wa), fb = __half22float2(wb);
            s += v.x * fa.x + v.y * fa.y + v.z * fb.x + v.w * fb.y;
        }
        if (lane < 4) {
            const int idx = 192 + lane;
            float4  v  = xr[idx];
            __half2 wa = wr[idx * 2];
            __half2 wb = wr[idx * 2 + 1];
            float2 fa = __half22float2(wa), fb = __half22float2(wb);
            s += v.x * fa.x + v.y * fa.y + v.z * fb.x + v.w * fb.y;
        }
#pragma unroll
        for (int d = 16; d; d >>= 1)
            s += __shfl_xor_sync(0xFFFFFFFFu, s, d);
        if (lane == 0)
            g_h[(size_t)row * DH + n] = (int8_t)tern_i(s + b1[n]);
    }
}

// ============================================================================
// Head: logits = g_h @ tern(w2)^T + b2 ; log_softmax. 4 threads per row.
// ============================================================================
__global__ __launch_bounds__(256)
void head_kernel(const float* __restrict__ w2,
                 const float* __restrict__ b2,
                 float* __restrict__ out) {
    __shared__ int   q2p[DOUT][DH / 4];
    __shared__ float b2s[DOUT];

    const int tid = threadIdx.x;
    for (int i = tid; i < DOUT * (DH / 4); i += 256) {
        const int o = i / (DH / 4);
        const int w = i % (DH / 4);
        int word = 0;
#pragma unroll
        for (int j = 0; j < 4; j++) {
            int t = tern_i(w2[o * DH + w * 4 + j]);
            word |= (t & 0xFF) << (8 * j);
        }
        q2p[o][w] = word;
    }
    if (tid < DOUT) b2s[tid] = b2[tid];
    __syncthreads();

    const int gidx   = blockIdx.x * 256 + tid;
    const size_t row = (size_t)(gidx >> 2);
    const int q      = gidx & 3;
    const uint4* hp  = (const uint4*)(g_h + row * DH) + q * 5;

    int acc[DOUT];
#pragma unroll
    for (int o = 0; o < DOUT; o++) acc[o] = 0;

#pragma unroll
    for (int c = 0; c < 5; c++) {
        uint4 v = hp[c];
        const int w = q * 20 + c * 4;
#pragma unroll
        for (int o = 0; o < DOUT; o++) {
            acc[o] = __dp4a((int)v.x, q2p[o][w + 0], acc[o]);
            acc[o] = __dp4a((int)v.y, q2p[o][w + 1], acc[o]);
            acc[o] = __dp4a((int)v.z, q2p[o][w + 2], acc[o]);
            acc[o] = __dp4a((int)v.w, q2p[o][w + 3], acc[o]);
        }
    }
#pragma unroll
    for (int o = 0; o < DOUT; o++) {
        acc[o] += __shfl_xor_sync(0xFFFFFFFFu, acc[o], 1);
        acc[o] += __shfl_xor_sync(0xFFFFFFFFu, acc[o], 2);
    }

    if (q == 0) {
        float lg[DOUT];
        float m = -1e30f;
#pragma unroll
        for (int o = 0; o < DOUT; o++) {
            lg[o] = (float)acc[o] + b2s[o];
            m = fmaxf(m, lg[o]);
        }
        float s = 0.0f;
#pragma unroll
        for (int o = 0; o < DOUT; o++) s += expf(lg[o] - m);
        const float lse = m + logf(s);
        float* op = out + row * DOUT;
#pragma unroll
        for (int o = 0; o < DOUT; o++) op[o] = lg[o] - lse;
    }
}

// ============================================================================
extern "C" void kernel_launch(void* const* d_in, const int* in_sizes, int n_in,
                              void* d_out, int out_size) {
    const float* x  = (const float*)d_in[0];
    const float* w1 = (const float*)d_in[1];
    const float* b1 = (const float*)d_in[2];
    const float* w2 = (const float*)d_in[3];
    const float* b2 = (const float*)d_in[4];
    float* out = (float*)d_out;

    cudaFuncSetAttribute(gemm1_hmma,
                         cudaFuncAttributeMaxDynamicSharedMemorySize, SMEM_DYN);

    prep_w1<<<(DH * DIN / 2 + 255) / 256, 256>>>(w1);
    gemm1_hmma<<<BATCH / BM, 512, SMEM_DYN>>>(x, b1);
    corr_kernel<<<2048, 256>>>(x, b1);
    head_kernel<<<BATCH * 4 / 256, 256>>>(w2, b2, out);
}